// round 8
// baseline (speedup 1.0000x reference)
#include <cuda_runtime.h>
#include <cstdint>

// Problem constants
#define B_    2
#define S_    2048
#define HID_  2048
#define NH_   32
#define NKV_  8
#define HD_   64
#define NREP_ 4
#define SCALING_ 0.125f

#define NQ_  (NH_ * HD_)               // 2048
#define NK_  (NKV_ * HD_)              // 512
#define NQK_ (NQ_ + NK_)               // 2560
#define NQKV_ (NQ_ + 2 * NK_)          // 3072

// d_out layout: [B*S*HID] projected output, then [B*NH*S*S] attn_weights
#define OUT_W_OFFSET ((long long)B_ * S_ * HID_)

// ---------------------------------------------------------------------------
// Scratch (device globals; no allocations allowed)
// NOTE: g_q / g_k hold the head-dim PERMUTED layout (p -> original channel
// (p&1)*32 + p/2). The logits GEMM contracts over this dim for both q and k,
// so the permutation cancels. g_v / g_ao are in natural layout.
// ---------------------------------------------------------------------------
__device__ __align__(16) float g_q [(size_t)B_ * NH_  * S_ * HD_];   // [b,h,s,p]
__device__ __align__(16) float g_k [(size_t)B_ * NKV_ * S_ * HD_];   // [b,kh,s,p]
__device__ __align__(16) float g_v [(size_t)B_ * NKV_ * S_ * HD_];   // [b,kh,s,d]
__device__ __align__(16) float g_ao[(size_t)B_ * S_ * NH_ * HD_];    // [b,s,h*HD+d]

// ---------------------------------------------------------------------------
// bf16 helpers
// ---------------------------------------------------------------------------
__device__ __forceinline__ uint16_t f2bf(float x) {
    uint16_t r;
    asm("cvt.rn.bf16.f32 %0, %1;" : "=h"(r) : "f"(x));
    return r;
}
__device__ __forceinline__ float bf2f(uint16_t h) {
    return __uint_as_float((uint32_t)h << 16);
}
__device__ __forceinline__ uint32_t packbf(uint16_t lo, uint16_t hi) {
    return (uint32_t)lo | ((uint32_t)hi << 16);
}
// Split x = hi + lo (both bf16), pack two consecutive elements into u32 pairs.
__device__ __forceinline__ void split2(float x, float y, uint32_t& ph,
                                       uint32_t& pl) {
    uint16_t hx = f2bf(x), hy = f2bf(y);
    uint16_t lx = f2bf(x - bf2f(hx)), ly = f2bf(y - bf2f(hy));
    ph = packbf(hx, hy);
    pl = packbf(lx, ly);
}

__device__ __forceinline__ void mma_bf16(float c[4], const uint32_t a[4],
                                         const uint32_t b[2]) {
    asm volatile(
        "mma.sync.aligned.m16n8k16.row.col.f32.bf16.bf16.f32 "
        "{%0,%1,%2,%3},{%4,%5,%6,%7},{%8,%9},{%0,%1,%2,%3};"
        : "+f"(c[0]), "+f"(c[1]), "+f"(c[2]), "+f"(c[3])
        : "r"(a[0]), "r"(a[1]), "r"(a[2]), "r"(a[3]), "r"(b[0]), "r"(b[1]));
}

// ---------------------------------------------------------------------------
// Epilogue functors
// ---------------------------------------------------------------------------
struct EpiQKV {  // fused projection epilogue: route by global n (perm layout)
    __device__ __forceinline__ void operator()(int z, int m, int n, float v) const {
        const int b = m / S_, s = m % S_;
        if (n < NQ_) {
            const int h = n / HD_, d = n % HD_;
            g_q[(((long long)b * NH_ + h) * S_ + s) * HD_ + d] = v;
        } else if (n < NQK_) {
            const int nn = n - NQ_;
            const int h = nn / HD_, d = nn % HD_;
            g_k[(((long long)b * NKV_ + h) * S_ + s) * HD_ + d] = v;
        } else {
            const int nn = n - NQK_;
            const int h = nn / HD_, d = nn % HD_;
            g_v[(((long long)b * NKV_ + h) * S_ + s) * HD_ + d] = v;
        }
    }
};
struct EpiLogits {
    float* w;  // d_out + OUT_W_OFFSET, layout [b,h,sq,sk]
    __device__ __forceinline__ void operator()(int z, int m, int n, float v) const {
        w[((long long)z * S_ + m) * S_ + n] = v * SCALING_;
    }
};
struct EpiOut {
    float* o;  // d_out, layout [b,s,hid] row-major
    __device__ __forceinline__ void operator()(int z, int m, int n, float v) const {
        o[(long long)m * HID_ + n] = v;
    }
};

// ---------------------------------------------------------------------------
// bf16 tensor-core GEMM (m16n8k16), 3-term bf16 error compensation,
// double-buffered smem (one barrier per K-tile), register-prefetch loads.
//   C[M,N] = A[M,K] * B^T   (B stored [N,K]; NT only in this build)
// MULTI: three stacked B matrices (B | B2 | B3) along N, 128-aligned splits.
// ROPE : (QKV launch) permute B rows within each 64-wide head so that output
//        pair (c, c+1) = original channels (d, d+32); apply RoPE to the
//        accumulator pair in the epilogue for columns c < ns2 (Q and K).
//        cos[d+32] == cos[d] per the reference's concat(freqs,freqs).
// CSKIP: skip tiles fully above the causal diagonal (logits).
// Fragment maps (g = lane/4, q = lane%4; u32 = packed bf16 K-pair):
//   A(16x16): a0=[g][q] a1=[g+8][q] a2=[g][q+4] a3=[g+8][q+4]
//   B(16x8) : b0=[n][q] b1=[n][q+4]
//   C(16x8) : c0=(g,2q) c1=(g,2q+1) c2=(g+8,2q) c3=(g+8,2q+1)
// Smem pad 12 u32/row -> fragment address g*12+q covers all 32 banks.
// Pipeline: prefetch next(GMEM->reg) | compute(buf) | store(reg->smem[buf^1])
// | BAR.  Stores never touch the buffer being read this iteration.
// ---------------------------------------------------------------------------
template <int BM, int BN, int WARPS_M, int WARPS_N, bool MULTI, bool ROPE,
          bool CSKIP, class Epi>
__global__ __launch_bounds__(256, 1) void gemm_bf16x3(
    const float* __restrict__ A, const float* __restrict__ Bm, int M, int N,
    int K, long long sAb, long long sBb, int bRep, Epi epi,
    const float* __restrict__ B2 = nullptr,
    const float* __restrict__ B3 = nullptr, int ns1 = 0, int ns2 = 0,
    const float* __restrict__ cs = nullptr,
    const float* __restrict__ sn = nullptr) {
    constexpr int BK = 16;
    constexpr int LDS_ = 12;  // u32 pairs per row (8 used + 4 pad)
    constexpr int WM = BM / WARPS_M;
    constexpr int WN = BN / WARPS_N;
    constexpr int MT = WM / 16;
    constexpr int NTL = WN / 8;
    constexpr int NA = BM / 64;   // A float4/thread
    constexpr int NB = BN / 64;   // B float4/thread

    const int z  = blockIdx.z;
    const int m0 = blockIdx.y * BM;
    const int n0 = blockIdx.x * BN;
    if (CSKIP && n0 >= m0 + BM) return;

    const float* Ab = A + (long long)z * sAb;
    const float* Bb;
    int nB;
    if (MULTI) {
        if (n0 < ns1)      { Bb = Bm; nB = n0; }
        else if (n0 < ns2) { Bb = B2; nB = n0 - ns1; }
        else               { Bb = B3; nB = n0 - ns2; }
    } else {
        Bb = Bm + (long long)(z / bRep) * sBb;
        nB = n0;
    }
    // Permute B rows (output channels) for Q/K: row p loads channel
    // (p&1)*32 + p/2 within its 64-wide head. Uniform per tile (splits
    // are 128-aligned).
    const bool doPerm = ROPE && (n0 < ns2);

    __shared__ uint32_t Ah[2][BM][LDS_], Al[2][BM][LDS_];
    __shared__ uint32_t Bh[2][BN][LDS_], Bl[2][BN][LDS_];

    const int t    = threadIdx.x;
    const int warp = t >> 5;
    const int lane = t & 31;
    const int qr = lane >> 2;
    const int qc = lane & 3;
    const int wm = warp / WARPS_N;
    const int wn = warp % WARPS_N;

    float acc[MT][NTL][4];
#pragma unroll
    for (int i = 0; i < MT; i++)
#pragma unroll
        for (int j = 0; j < NTL; j++)
#pragma unroll
            for (int e = 0; e < 4; e++) acc[i][j][e] = 0.f;

    float4 pa[NA], pb[NB];

    auto loadA = [&](int k0) {
#pragma unroll
        for (int s = 0; s < NA; s++) {
            const int row = s * 64 + (t >> 2);
            const int c4  = (t & 3) * 4;
            pa[s] = *(const float4*)&Ab[(long long)(m0 + row) * K + k0 + c4];
        }
    };
    auto loadB = [&](int k0) {
#pragma unroll
        for (int s = 0; s < NB; s++) {
            const int row = s * 64 + (t >> 2);
            const int c4  = (t & 3) * 4;
            int rw = nB + row;
            if (ROPE && doPerm) {
                const int head = rw >> 6, p = rw & 63;
                rw = (head << 6) | ((p & 1) << 5) | (p >> 1);
            }
            pb[s] = *(const float4*)&Bb[(long long)rw * K + k0 + c4];
        }
    };
    auto storeA = [&](int buf) {
#pragma unroll
        for (int s = 0; s < NA; s++) {
            const int row = s * 64 + (t >> 2);
            const int p0  = (t & 3) * 2;
            uint32_t h0, l0, h1, l1;
            split2(pa[s].x, pa[s].y, h0, l0);
            split2(pa[s].z, pa[s].w, h1, l1);
            Ah[buf][row][p0] = h0;     Ah[buf][row][p0 + 1] = h1;
            Al[buf][row][p0] = l0;     Al[buf][row][p0 + 1] = l1;
        }
    };
    auto storeB = [&](int buf) {
#pragma unroll
        for (int s = 0; s < NB; s++) {
            const int row = s * 64 + (t >> 2);
            const int p0  = (t & 3) * 2;
            uint32_t h0, l0, h1, l1;
            split2(pb[s].x, pb[s].y, h0, l0);
            split2(pb[s].z, pb[s].w, h1, l1);
            Bh[buf][row][p0] = h0;     Bh[buf][row][p0 + 1] = h1;
            Bl[buf][row][p0] = l0;     Bl[buf][row][p0 + 1] = l1;
        }
    };

    const int nk = K / BK;

    loadA(0);
    loadB(0);
    storeA(0);
    storeB(0);
    __syncthreads();

    for (int kt = 0; kt < nk; kt++) {
        const int buf = kt & 1;

        if (kt + 1 < nk) {  // prefetch next tile into registers
            loadA((kt + 1) * BK);
            loadB((kt + 1) * BK);
        }

        uint32_t afh[MT][4], afl[MT][4];
#pragma unroll
        for (int i = 0; i < MT; i++) {
            const int r = wm * WM + i * 16 + qr;
            afh[i][0] = Ah[buf][r][qc];     afh[i][1] = Ah[buf][r + 8][qc];
            afh[i][2] = Ah[buf][r][qc + 4]; afh[i][3] = Ah[buf][r + 8][qc + 4];
            afl[i][0] = Al[buf][r][qc];     afl[i][1] = Al[buf][r + 8][qc];
            afl[i][2] = Al[buf][r][qc + 4]; afl[i][3] = Al[buf][r + 8][qc + 4];
        }
        uint32_t bfh[NTL][2], bfl[NTL][2];
#pragma unroll
        for (int j = 0; j < NTL; j++) {
            const int n = wn * WN + j * 8 + qr;
            bfh[j][0] = Bh[buf][n][qc]; bfh[j][1] = Bh[buf][n][qc + 4];
            bfl[j][0] = Bl[buf][n][qc]; bfl[j][1] = Bl[buf][n][qc + 4];
        }
#pragma unroll
        for (int i = 0; i < MT; i++)
#pragma unroll
            for (int j = 0; j < NTL; j++) {
                mma_bf16(acc[i][j], afh[i], bfl[j]);
                mma_bf16(acc[i][j], afl[i], bfh[j]);
                mma_bf16(acc[i][j], afh[i], bfh[j]);
            }

        if (kt + 1 < nk) {  // stage next tile into the other buffer
            storeA(buf ^ 1);
            storeB(buf ^ 1);
            __syncthreads();
        }
    }

#pragma unroll
    for (int i = 0; i < MT; i++)
#pragma unroll
        for (int j = 0; j < NTL; j++) {
            const int r = m0 + wm * WM + i * 16 + qr;
            const int c = n0 + wn * WN + j * 8 + 2 * qc;
            float v0 = acc[i][j][0], v1 = acc[i][j][1];   // row r,   cols c,c+1
            float w0 = acc[i][j][2], w1 = acc[i][j][3];   // row r+8, cols c,c+1
            if (ROPE && c < ns2) {
                // pair (c, c+1) = original channels (d, d+32), d = (c%64)/2
                const int d = (c & 63) >> 1;
                const float c0 = cs[(long long)r * HD_ + d];
                const float s0 = sn[(long long)r * HD_ + d];
                const float c1 = cs[(long long)(r + 8) * HD_ + d];
                const float s1 = sn[(long long)(r + 8) * HD_ + d];
                const float nv0 = v0 * c0 - v1 * s0;
                const float nv1 = v1 * c0 + v0 * s0;
                const float nw0 = w0 * c1 - w1 * s1;
                const float nw1 = w1 * c1 + w0 * s1;
                v0 = nv0; v1 = nv1; w0 = nw0; w1 = nw1;
            }
            epi(z, r,     c,     v0);
            epi(z, r,     c + 1, v1);
            epi(z, r + 8, c,     w0);
            epi(z, r + 8, c + 1, w1);
        }
}

// ---------------------------------------------------------------------------
// Fused causal softmax + P@V (double-buffered V staging).
// One CTA per (z = b*NH+h, 128-query block). 256 threads, 8 warps; warp w owns
// query rows m0+16w .. m0+16w+15 (its own MMA A rows).
// Pass 1: per-row max & sum over the valid prefix (coalesced, warp per row).
// Pass 2: per 16-wide k-tile: each thread re-reads its A-fragment logit pairs
// (L2-hot), computes p = exp(v-mx)*inv (exact 0 above the diagonal), writes
// fp32 p back to w, splits p to bf16 hi/lo, and runs the 3-MMA compensated
// m16n8k16 against the staged V tile. Tail (k >= m0+128) is zero-filled
// (pure stores; replay-safe because it is never read).
// ---------------------------------------------------------------------------
__global__ __launch_bounds__(256, 1) void softmax_pv_kernel(
    float* __restrict__ w, const float* __restrict__ V) {
    const int m0 = blockIdx.x * 128;
    const int z  = blockIdx.y;
    const int b  = z / NH_, h = z % NH_;
    float* wz = w + (long long)z * S_ * S_;
    const float* Vb = V + ((long long)(b * NKV_ + h / NREP_) * S_) * HD_;

    __shared__ float s_mx[128], s_inv[128];
    __shared__ uint32_t Vh[2][64][12], Vl[2][64][12];

    const int t    = threadIdx.x;
    const int warp = t >> 5;
    const int lane = t & 31;
    const int g = lane >> 2;
    const int q = lane & 3;

    // ---- pass 1: row max & sum over valid prefix [0, m]
    for (int r = 0; r < 16; r++) {
        const int row = m0 + warp * 16 + r;
        const float* rw = wz + (long long)row * S_;
        const int nv = row + 1;
        float mx = -1e30f;
        for (int j = lane; j < nv; j += 32) mx = fmaxf(mx, rw[j]);
#pragma unroll
        for (int o = 16; o; o >>= 1) mx = fmaxf(mx, __shfl_xor_sync(~0u, mx, o));
        float sum = 0.f;
        for (int j = lane; j < nv; j += 32) sum += __expf(rw[j] - mx);
#pragma unroll
        for (int o = 16; o; o >>= 1) sum += __shfl_xor_sync(~0u, sum, o);
        if (lane == 0) {
            s_mx[warp * 16 + r]  = mx;
            s_inv[warp * 16 + r] = 1.0f / sum;
        }
    }
    __syncthreads();

    // ---- pass 2 setup: this thread's two fragment rows
    const int rl0 = warp * 16 + g;       // local row (A fragment rows g, g+8)
    const int rl1 = rl0 + 8;
    const int mg0 = m0 + rl0, mg1 = m0 + rl1;   // global query indices
    const float mx0 = s_mx[rl0], iv0 = s_inv[rl0];
    const float mx1 = s_mx[rl1], iv1 = s_inv[rl1];
    float* row0 = wz + (long long)mg0 * S_;
    float* row1 = wz + (long long)mg1 * S_;

    float acc[8][4];
#pragma unroll
    for (int j = 0; j < 8; j++)
#pragma unroll
        for (int e = 0; e < 4; e++) acc[j][e] = 0.f;

    const int nkt = (m0 + 128) / 16;  // k-tiles up to the diagonal block end

    float4 pv;  // V prefetch register
    auto loadV = [&](int kt) {
        pv = *(const float4*)&Vb[(long long)(kt * 16 + (t >> 4)) * HD_ +
                                 (t & 15) * 4];
    };
    auto stageV = [&](int buf) {
        const int k  = t >> 4;
        const int n4 = (t & 15) * 4;
        const float xs[4] = {pv.x, pv.y, pv.z, pv.w};
#pragma unroll
        for (int u = 0; u < 4; u++) {
            uint16_t hh = f2bf(xs[u]);
            uint16_t ll = f2bf(xs[u] - bf2f(hh));
            ((uint16_t*)Vh[buf][n4 + u])[k] = hh;
            ((uint16_t*)Vl[buf][n4 + u])[k] = ll;
        }
    };

    loadV(0);
    stageV(0);
    __syncthreads();

    for (int kt = 0; kt < nkt; kt++) {
        const int buf = kt & 1;
        if (kt + 1 < nkt) loadV(kt + 1);

        const int k0 = kt * 16;
        // read this thread's A-fragment logit pairs (L2-hot re-read)
        float2 v00 = *(float2*)&row0[k0 + 2 * q];
        float2 v02 = *(float2*)&row0[k0 + 2 * q + 8];
        float2 v10 = *(float2*)&row1[k0 + 2 * q];
        float2 v12 = *(float2*)&row1[k0 + 2 * q + 8];

        // softmax values (exact zeros above the diagonal)
        const int j0 = k0 + 2 * q, j2 = j0 + 8;
        float p00x = (j0     <= mg0) ? __expf(v00.x - mx0) * iv0 : 0.f;
        float p00y = (j0 + 1 <= mg0) ? __expf(v00.y - mx0) * iv0 : 0.f;
        float p02x = (j2     <= mg0) ? __expf(v02.x - mx0) * iv0 : 0.f;
        float p02y = (j2 + 1 <= mg0) ? __expf(v02.y - mx0) * iv0 : 0.f;
        float p10x = (j0     <= mg1) ? __expf(v10.x - mx1) * iv1 : 0.f;
        float p10y = (j0 + 1 <= mg1) ? __expf(v10.y - mx1) * iv1 : 0.f;
        float p12x = (j2     <= mg1) ? __expf(v12.x - mx1) * iv1 : 0.f;
        float p12y = (j2 + 1 <= mg1) ? __expf(v12.y - mx1) * iv1 : 0.f;

        // write normalized weights
        *(float2*)&row0[j0] = make_float2(p00x, p00y);
        *(float2*)&row0[j2] = make_float2(p02x, p02y);
        *(float2*)&row1[j0] = make_float2(p10x, p10y);
        *(float2*)&row1[j2] = make_float2(p12x, p12y);

        // build A fragments (hi/lo)
        uint32_t afh[4], afl[4];
        split2(p00x, p00y, afh[0], afl[0]);
        split2(p10x, p10y, afh[1], afl[1]);
        split2(p02x, p02y, afh[2], afl[2]);
        split2(p12x, p12y, afh[3], afl[3]);

#pragma unroll
        for (int j = 0; j < 8; j++) {
            const int n = j * 8 + g;
            uint32_t bfh[2] = {Vh[buf][n][q], Vh[buf][n][q + 4]};
            uint32_t bfl[2] = {Vl[buf][n][q], Vl[buf][n][q + 4]};
            mma_bf16(acc[j], afh, bfl);
            mma_bf16(acc[j], afl, bfh);
            mma_bf16(acc[j], afh, bfh);
        }

        if (kt + 1 < nkt) {  // stage next V tile into the other buffer
            stageV(buf ^ 1);
            __syncthreads();
        }
    }

    // ---- zero-fill tail: columns [m0+128, S) for all 128 rows (stores only)
    {
        const int tail0 = m0 + 128;
        if (tail0 < S_) {
            const int rloc = t >> 1;
            const int half = t & 1;
            float* rw = wz + (long long)(m0 + rloc) * S_ + tail0;
            const int ntail = S_ - tail0;
            const float4 z4 = make_float4(0.f, 0.f, 0.f, 0.f);
            for (int j = half * 4; j < ntail; j += 8) *(float4*)&rw[j] = z4;
        }
    }

    // ---- epilogue: acc -> g_ao [b, s, h*HD + d]
    const long long base0 = ((long long)(b * S_ + mg0)) * (NH_ * HD_) + h * HD_;
    const long long base1 = ((long long)(b * S_ + mg1)) * (NH_ * HD_) + h * HD_;
#pragma unroll
    for (int j = 0; j < 8; j++) {
        const int c = j * 8 + 2 * q;
        *(float2*)&g_ao[base0 + c] = make_float2(acc[j][0], acc[j][1]);
        *(float2*)&g_ao[base1 + c] = make_float2(acc[j][2], acc[j][3]);
    }
}

// ---------------------------------------------------------------------------
// Launch
// ---------------------------------------------------------------------------
extern "C" void kernel_launch(void* const* d_in, const int* in_sizes, int n_in,
                              void* d_out, int out_size) {
    const float* hidden = (const float*)d_in[0];
    const float* cs     = (const float*)d_in[1];
    const float* sn     = (const float*)d_in[2];
    // d_in[3] = attention_mask: causal 0/-1e9, applied analytically (unused)
    const float* Wq = (const float*)d_in[4];
    const float* Wk = (const float*)d_in[5];
    const float* Wv = (const float*)d_in[6];
    const float* Wo = (const float*)d_in[7];

    float* out = (float*)d_out;
    float* w   = out + OUT_W_OFFSET;

    float *pq, *pk, *pv, *pao;
    cudaGetSymbolAddress((void**)&pq,  g_q);
    cudaGetSymbolAddress((void**)&pk,  g_k);
    cudaGetSymbolAddress((void**)&pv,  g_v);
    cudaGetSymbolAddress((void**)&pao, g_ao);

    const int M = B_ * S_;  // 4096

    // 1) Fused QKV projection + RoPE: X @ [Wq | Wk | Wv]^T, N = 3072.
    //    Q/K head-dims stored permuted (pairs adjacent); RoPE applied in the
    //    epilogue using cos/sin (cos[d+32]==cos[d]).
    gemm_bf16x3<128, 128, 2, 4, true, true, false, EpiQKV>
        <<<dim3(NQKV_ / 128, M / 128, 1), 256>>>(
            hidden, Wq, M, NQKV_, HID_, 0, 0, 1, EpiQKV{}, Wk, Wv, NQ_, NQK_,
            cs, sn);

    // 2) logits = q @ k^T * scale (batched over B*NH; causal tile skip).
    //    Contraction over the permuted head-dim: invariant.
    gemm_bf16x3<128, 128, 2, 4, false, false, true, EpiLogits>
        <<<dim3(S_ / 128, S_ / 128, B_ * NH_), 256>>>(
            pq, pk, S_, S_, HD_, (long long)S_ * HD_, (long long)S_ * HD_,
            NREP_, EpiLogits{w});

    // 3) fused causal softmax + P@V (writes attn_weights and g_ao)
    softmax_pv_kernel<<<dim3(S_ / 128, B_ * NH_), 256>>>(w, pv);

    // 4) out = attn_out @ Wo^T
    gemm_bf16x3<128, 128, 2, 4, false, false, false, EpiOut>
        <<<dim3(HID_ / 128, M / 128, 1), 256>>>(
            pao, Wo, M, HID_, NH_ * HD_, 0, 0, 1, EpiOut{out});
}

// round 10
// speedup vs baseline: 1.1144x; 1.1144x over previous
#include <cuda_runtime.h>
#include <cstdint>

// Problem constants
#define B_    2
#define S_    2048
#define HID_  2048
#define NH_   32
#define NKV_  8
#define HD_   64
#define NREP_ 4
#define SCALING_ 0.125f

#define NQ_  (NH_ * HD_)               // 2048
#define NK_  (NKV_ * HD_)              // 512
#define NQK_ (NQ_ + NK_)               // 2560
#define NQKV_ (NQ_ + 2 * NK_)          // 3072

// d_out layout: [B*S*HID] projected output, then [B*NH*S*S] attn_weights
#define OUT_W_OFFSET ((long long)B_ * S_ * HID_)

// ---------------------------------------------------------------------------
// Scratch (device globals; no allocations allowed)
// Q/K/P(ao) are stored PRE-SPLIT as packed bf16 hi/lo u32 K-pairs, in exactly
// the layout the consuming GEMM's smem wants. Q/K use the head-dim PERMUTED
// order (pair p -> original channels (d, d+32), d = p/2); the logits GEMM
// contracts over this dim for both operands, so the permutation cancels.
// V is stored as bf16 hi/lo elements (natural layout).
// ---------------------------------------------------------------------------
__device__ uint32_t g_qh[(size_t)B_ * NH_  * S_ * (HD_ / 2)];
__device__ uint32_t g_ql[(size_t)B_ * NH_  * S_ * (HD_ / 2)];
__device__ uint32_t g_kh[(size_t)B_ * NKV_ * S_ * (HD_ / 2)];
__device__ uint32_t g_kl[(size_t)B_ * NKV_ * S_ * (HD_ / 2)];
__device__ uint16_t g_vh[(size_t)B_ * NKV_ * S_ * HD_];
__device__ uint16_t g_vl[(size_t)B_ * NKV_ * S_ * HD_];
__device__ uint32_t g_aoh[(size_t)B_ * S_ * (NH_ * HD_ / 2)];
__device__ uint32_t g_aol[(size_t)B_ * S_ * (NH_ * HD_ / 2)];

// ---------------------------------------------------------------------------
// bf16 helpers
// ---------------------------------------------------------------------------
__device__ __forceinline__ uint16_t f2bf(float x) {
    uint16_t r;
    asm("cvt.rn.bf16.f32 %0, %1;" : "=h"(r) : "f"(x));
    return r;
}
__device__ __forceinline__ float bf2f(uint16_t h) {
    return __uint_as_float((uint32_t)h << 16);
}
__device__ __forceinline__ uint32_t packbf(uint16_t lo, uint16_t hi) {
    return (uint32_t)lo | ((uint32_t)hi << 16);
}
__device__ __forceinline__ void split2(float x, float y, uint32_t& ph,
                                       uint32_t& pl) {
    uint16_t hx = f2bf(x), hy = f2bf(y);
    uint16_t lx = f2bf(x - bf2f(hx)), ly = f2bf(y - bf2f(hy));
    ph = packbf(hx, hy);
    pl = packbf(lx, ly);
}

__device__ __forceinline__ void mma_bf16(float c[4], const uint32_t a[4],
                                         const uint32_t b[2]) {
    asm volatile(
        "mma.sync.aligned.m16n8k16.row.col.f32.bf16.bf16.f32 "
        "{%0,%1,%2,%3},{%4,%5,%6,%7},{%8,%9},{%0,%1,%2,%3};"
        : "+f"(c[0]), "+f"(c[1]), "+f"(c[2]), "+f"(c[3])
        : "r"(a[0]), "r"(a[1]), "r"(a[2]), "r"(a[3]), "r"(b[0]), "r"(b[1]));
}

// ---------------------------------------------------------------------------
// Pair epilogues: epi(z, row, col_even, v(col), v(col+1))
// ---------------------------------------------------------------------------
struct EpiQKV {  // route by n; store presplit pairs (q/k) or bf16 elems (v)
    __device__ __forceinline__ void operator()(int z, int m, int n, float x,
                                               float y) const {
        const int b = m >> 11, s = m & (S_ - 1);
        if (n < NQ_) {
            const int h = n >> 6, pr = (n & 63) >> 1;
            uint32_t hh, ll;
            split2(x, y, hh, ll);
            const size_t idx =
                (((size_t)b * NH_ + h) * S_ + s) * (HD_ / 2) + pr;
            g_qh[idx] = hh;
            g_ql[idx] = ll;
        } else if (n < NQK_) {
            const int nn = n - NQ_;
            const int h = nn >> 6, pr = (nn & 63) >> 1;
            uint32_t hh, ll;
            split2(x, y, hh, ll);
            const size_t idx =
                (((size_t)b * NKV_ + h) * S_ + s) * (HD_ / 2) + pr;
            g_kh[idx] = hh;
            g_kl[idx] = ll;
        } else {
            const int nn = n - NQK_;
            const int h = nn >> 6, d = nn & 63;
            const size_t idx = (((size_t)b * NKV_ + h) * S_ + s) * HD_ + d;
            uint16_t hx = f2bf(x), hy = f2bf(y);
            uint16_t lx = f2bf(x - bf2f(hx)), ly = f2bf(y - bf2f(hy));
            *(uint32_t*)&g_vh[idx] = packbf(hx, hy);
            *(uint32_t*)&g_vl[idx] = packbf(lx, ly);
        }
    }
};
struct EpiLogits {
    float* w;  // d_out + OUT_W_OFFSET, layout [b,h,sq,sk]
    __device__ __forceinline__ void operator()(int z, int m, int n, float x,
                                               float y) const {
        *(float2*)&w[((long long)z * S_ + m) * S_ + n] =
            make_float2(x * SCALING_, y * SCALING_);
    }
};
struct EpiOut {
    float* o;  // d_out, layout [b,s,hid]
    __device__ __forceinline__ void operator()(int z, int m, int n, float x,
                                               float y) const {
        *(float2*)&o[(long long)m * HID_ + n] = make_float2(x, y);
    }
};

// ---------------------------------------------------------------------------
// bf16 tensor-core GEMM (m16n8k16), 3-term bf16 error compensation,
// double-buffered smem, register-prefetch loads, occupancy-2 tiles.
//   C[M,N] = A[M,K] * B^T   (NT)
// BM=128, BN=64, 8 warps (4x2): 32 acc regs/thread.
// APS : A operand is presplit packed pairs (Aph/Apl), KP = K/2 per row.
// BPS : B operand presplit (Bph/Bpl).
// MULTI: three stacked fp32 B matrices (Bf|B2|B3) along N, 64-aligned splits.
// ROPE : permute fp32 B rows within each 64-wide head (pair layout) and apply
//        RoPE to accumulator pairs in the epilogue for cols < ns2 (Q and K);
//        cos[d+32] == cos[d].
// CSKIP: skip tiles fully above the causal diagonal.
// Fragment maps (g = lane/4, q = lane%4; u32 = packed bf16 K-pair):
//   A: a0=[g][q] a1=[g+8][q] a2=[g][q+4] a3=[g+8][q+4]
//   B: b0=[n][q] b1=[n][q+4]
//   C: c0=(g,2q) c1=(g,2q+1) c2=(g+8,2q) c3=(g+8,2q+1)
// Smem pad 12 u32/row; MMA loop is term-outer (8 independent MMAs between
// accumulator reuses).
// ---------------------------------------------------------------------------
template <int BM, int BN, int WARPS_M, int WARPS_N, bool APS, bool BPS,
          bool MULTI, bool ROPE, bool CSKIP, class Epi>
__global__ __launch_bounds__(256, 2) void gemm_bf16x3(
    const float* __restrict__ Af, const uint32_t* __restrict__ Aph,
    const uint32_t* __restrict__ Apl, const float* __restrict__ Bf,
    const uint32_t* __restrict__ Bph, const uint32_t* __restrict__ Bpl,
    int M, int N, int K, long long sAb, long long sBb, int bRep, Epi epi,
    const float* __restrict__ B2 = nullptr,
    const float* __restrict__ B3 = nullptr, int ns1 = 0, int ns2 = 0,
    const float* __restrict__ cs = nullptr,
    const float* __restrict__ sn = nullptr) {
    constexpr int BK = 16;
    constexpr int LDS_ = 12;
    constexpr int WM = BM / WARPS_M;   // 32
    constexpr int WN = BN / WARPS_N;   // 32
    constexpr int MT = WM / 16;        // 2
    constexpr int NTL = WN / 8;        // 4
    constexpr int NA = BM / 64;        // fp32 A float4/thread (2)

    const int z  = blockIdx.z;
    const int m0 = blockIdx.y * BM;
    const int n0 = blockIdx.x * BN;
    if (CSKIP && n0 >= m0 + BM) return;

    const int KP = K >> 1;  // pairs per row (presplit addressing)

    const float*    Afb = Af;
    const uint32_t* Aphb = Aph;
    const uint32_t* Aplb = Apl;
    if (APS) {
        Aphb += (long long)z * sAb;
        Aplb += (long long)z * sAb;
    } else if (Af) {
        Afb += (long long)z * sAb;
    }
    const float*    Bfb = Bf;
    const uint32_t* Bphb = Bph;
    const uint32_t* Bplb = Bpl;
    int nB = n0;
    if (BPS) {
        Bphb += (long long)(z / bRep) * sBb;
        Bplb += (long long)(z / bRep) * sBb;
    } else if (MULTI) {
        if (n0 < ns1)      { Bfb = Bf; nB = n0; }
        else if (n0 < ns2) { Bfb = B2; nB = n0 - ns1; }
        else               { Bfb = B3; nB = n0 - ns2; }
    } else if (Bf) {
        Bfb += (long long)(z / bRep) * sBb;
    }
    const bool doPerm = ROPE && MULTI && (n0 < ns2);

    __shared__ uint32_t Ah[2][BM][LDS_], Al[2][BM][LDS_];
    __shared__ uint32_t Bh[2][BN][LDS_], Bl[2][BN][LDS_];

    const int t    = threadIdx.x;
    const int warp = t >> 5;
    const int lane = t & 31;
    const int qr = lane >> 2;
    const int qc = lane & 3;
    const int wm = warp / WARPS_N;
    const int wn = warp % WARPS_N;

    float acc[MT][NTL][4];
#pragma unroll
    for (int i = 0; i < MT; i++)
#pragma unroll
        for (int j = 0; j < NTL; j++)
#pragma unroll
            for (int e = 0; e < 4; e++) acc[i][j][e] = 0.f;

    // prefetch registers
    float4 pa[NA];
    float4 pb;
    uint4 pah, pal;
    uint2 pbh, pbl;

    auto loadA = [&](int kt) {
        if (APS) {
            const int row = t >> 1, po = (t & 1) * 4;
            const long long off = (long long)(m0 + row) * KP + kt * 8 + po;
            pah = *(const uint4*)&Aphb[off];
            pal = *(const uint4*)&Aplb[off];
        } else {
            const int k0 = kt * BK;
#pragma unroll
            for (int s = 0; s < NA; s++) {
                const int row = s * 64 + (t >> 2);
                const int c4  = (t & 3) * 4;
                pa[s] =
                    *(const float4*)&Afb[(long long)(m0 + row) * K + k0 + c4];
            }
        }
    };
    auto loadB = [&](int kt) {
        if (BPS) {
            const int row = t >> 2, po = (t & 3) * 2;
            const long long off = (long long)(nB + row) * KP + kt * 8 + po;
            pbh = *(const uint2*)&Bphb[off];
            pbl = *(const uint2*)&Bplb[off];
        } else {
            const int k0 = kt * BK;
            const int row = t >> 2;
            const int c4  = (t & 3) * 4;
            int rw = nB + row;
            if (ROPE && doPerm) {
                const int head = rw >> 6, p = rw & 63;
                rw = (head << 6) | ((p & 1) << 5) | (p >> 1);
            }
            pb = *(const float4*)&Bfb[(long long)rw * K + k0 + c4];
        }
    };
    auto storeA = [&](int buf) {
        if (APS) {
            const int row = t >> 1, po = (t & 1) * 4;
            *(uint4*)&Ah[buf][row][po] = pah;
            *(uint4*)&Al[buf][row][po] = pal;
        } else {
#pragma unroll
            for (int s = 0; s < NA; s++) {
                const int row = s * 64 + (t >> 2);
                const int p0  = (t & 3) * 2;
                uint32_t h0, l0, h1, l1;
                split2(pa[s].x, pa[s].y, h0, l0);
                split2(pa[s].z, pa[s].w, h1, l1);
                Ah[buf][row][p0] = h0;  Ah[buf][row][p0 + 1] = h1;
                Al[buf][row][p0] = l0;  Al[buf][row][p0 + 1] = l1;
            }
        }
    };
    auto storeB = [&](int buf) {
        if (BPS) {
            const int row = t >> 2, po = (t & 3) * 2;
            *(uint2*)&Bh[buf][row][po] = pbh;
            *(uint2*)&Bl[buf][row][po] = pbl;
        } else {
            const int row = t >> 2;
            const int p0  = (t & 3) * 2;
            uint32_t h0, l0, h1, l1;
            split2(pb.x, pb.y, h0, l0);
            split2(pb.z, pb.w, h1, l1);
            Bh[buf][row][p0] = h0;  Bh[buf][row][p0 + 1] = h1;
            Bl[buf][row][p0] = l0;  Bl[buf][row][p0 + 1] = l1;
        }
    };

    const int nk = K / BK;

    loadA(0);
    loadB(0);
    storeA(0);
    storeB(0);
    __syncthreads();

    for (int kt = 0; kt < nk; kt++) {
        const int buf = kt & 1;

        if (kt + 1 < nk) {
            loadA(kt + 1);
            loadB(kt + 1);
        }

        uint32_t afh[MT][4], afl[MT][4];
#pragma unroll
        for (int i = 0; i < MT; i++) {
            const int r = wm * WM + i * 16 + qr;
            afh[i][0] = Ah[buf][r][qc];     afh[i][1] = Ah[buf][r + 8][qc];
            afh[i][2] = Ah[buf][r][qc + 4]; afh[i][3] = Ah[buf][r + 8][qc + 4];
            afl[i][0] = Al[buf][r][qc];     afl[i][1] = Al[buf][r + 8][qc];
            afl[i][2] = Al[buf][r][qc + 4]; afl[i][3] = Al[buf][r + 8][qc + 4];
        }
        uint32_t bfh[NTL][2], bfl[NTL][2];
#pragma unroll
        for (int j = 0; j < NTL; j++) {
            const int n = wn * WN + j * 8 + qr;
            bfh[j][0] = Bh[buf][n][qc]; bfh[j][1] = Bh[buf][n][qc + 4];
            bfl[j][0] = Bl[buf][n][qc]; bfl[j][1] = Bl[buf][n][qc + 4];
        }
        // term-outer: 8 independent MMAs between accumulator reuses
#pragma unroll
        for (int i = 0; i < MT; i++)
#pragma unroll
            for (int j = 0; j < NTL; j++) mma_bf16(acc[i][j], afh[i], bfl[j]);
#pragma unroll
        for (int i = 0; i < MT; i++)
#pragma unroll
            for (int j = 0; j < NTL; j++) mma_bf16(acc[i][j], afl[i], bfh[j]);
#pragma unroll
        for (int i = 0; i < MT; i++)
#pragma unroll
            for (int j = 0; j < NTL; j++) mma_bf16(acc[i][j], afh[i], bfh[j]);

        if (kt + 1 < nk) {
            storeA(buf ^ 1);
            storeB(buf ^ 1);
            __syncthreads();
        }
    }

#pragma unroll
    for (int i = 0; i < MT; i++)
#pragma unroll
        for (int j = 0; j < NTL; j++) {
            const int r = m0 + wm * WM + i * 16 + qr;
            const int c = n0 + wn * WN + j * 8 + 2 * qc;
            float v0 = acc[i][j][0], v1 = acc[i][j][1];
            float w0 = acc[i][j][2], w1 = acc[i][j][3];
            if (ROPE && c < ns2) {
                const int d = (c & 63) >> 1;  // pair = channels (d, d+32)
                const float c0 = cs[(long long)r * HD_ + d];
                const float s0 = sn[(long long)r * HD_ + d];
                const float c1 = cs[(long long)(r + 8) * HD_ + d];
                const float s1 = sn[(long long)(r + 8) * HD_ + d];
                const float nv0 = v0 * c0 - v1 * s0;
                const float nv1 = v1 * c0 + v0 * s0;
                const float nw0 = w0 * c1 - w1 * s1;
                const float nw1 = w1 * c1 + w0 * s1;
                v0 = nv0; v1 = nv1; w0 = nw0; w1 = nw1;
            }
            epi(z, r,     c, v0, v1);
            epi(z, r + 8, c, w0, w1);
        }
}

// ---------------------------------------------------------------------------
// Fused causal softmax + P@V (double-buffered V staging, presplit V input,
// presplit P(ao) output).
// One CTA per (z = b*NH+h, 128-query block). 8 warps; warp w owns query rows
// m0+16w..m0+16w+15. Pass 1: row max/sum over valid prefix. Pass 2: per
// 16-wide k-tile, re-read logits in A-fragment layout (L2-hot), apply
// softmax (exact 0 above diagonal), write fp32 weights, 3-MMA compensated
// P@V against staged bf16 V. Tail zero-filled (stores only, replay-safe).
// ---------------------------------------------------------------------------
__global__ __launch_bounds__(256, 2) void softmax_pv_kernel(
    float* __restrict__ w) {
    const int m0 = blockIdx.x * 128;
    const int z  = blockIdx.y;
    const int b  = z / NH_, h = z % NH_;
    float* wz = w + (long long)z * S_ * S_;
    const size_t vbase = (((size_t)b * NKV_ + h / NREP_) * S_) * HD_;

    __shared__ float s_mx[128], s_inv[128];
    __shared__ uint32_t Vh[2][64][12], Vl[2][64][12];

    const int t    = threadIdx.x;
    const int warp = t >> 5;
    const int lane = t & 31;
    const int g = lane >> 2;
    const int q = lane & 3;

    // ---- pass 1: row max & sum over valid prefix [0, row]
    for (int r = 0; r < 16; r++) {
        const int row = m0 + warp * 16 + r;
        const float* rw = wz + (long long)row * S_;
        const int nv = row + 1;
        float mx = -1e30f;
        for (int j = lane; j < nv; j += 32) mx = fmaxf(mx, rw[j]);
#pragma unroll
        for (int o = 16; o; o >>= 1) mx = fmaxf(mx, __shfl_xor_sync(~0u, mx, o));
        float sum = 0.f;
        for (int j = lane; j < nv; j += 32) sum += __expf(rw[j] - mx);
#pragma unroll
        for (int o = 16; o; o >>= 1) sum += __shfl_xor_sync(~0u, sum, o);
        if (lane == 0) {
            s_mx[warp * 16 + r]  = mx;
            s_inv[warp * 16 + r] = 1.0f / sum;
        }
    }
    __syncthreads();

    const int rl0 = warp * 16 + g;
    const int rl1 = rl0 + 8;
    const int mg0 = m0 + rl0, mg1 = m0 + rl1;
    const float mx0 = s_mx[rl0], iv0 = s_inv[rl0];
    const float mx1 = s_mx[rl1], iv1 = s_inv[rl1];
    float* row0 = wz + (long long)mg0 * S_;
    float* row1 = wz + (long long)mg1 * S_;

    float acc[8][4];
#pragma unroll
    for (int j = 0; j < 8; j++)
#pragma unroll
        for (int e = 0; e < 4; e++) acc[j][e] = 0.f;

    const int nkt = (m0 + 128) / 16;

    uint2 vh2, vl2;
    auto loadV = [&](int kt) {
        const size_t off =
            vbase + (size_t)(kt * 16 + (t >> 4)) * HD_ + (t & 15) * 4;
        vh2 = *(const uint2*)&g_vh[off];
        vl2 = *(const uint2*)&g_vl[off];
    };
    auto stageV = [&](int buf) {
        const int k  = t >> 4;
        const int n4 = (t & 15) * 4;
        ((uint16_t*)Vh[buf][n4 + 0])[k] = (uint16_t)vh2.x;
        ((uint16_t*)Vh[buf][n4 + 1])[k] = (uint16_t)(vh2.x >> 16);
        ((uint16_t*)Vh[buf][n4 + 2])[k] = (uint16_t)vh2.y;
        ((uint16_t*)Vh[buf][n4 + 3])[k] = (uint16_t)(vh2.y >> 16);
        ((uint16_t*)Vl[buf][n4 + 0])[k] = (uint16_t)vl2.x;
        ((uint16_t*)Vl[buf][n4 + 1])[k] = (uint16_t)(vl2.x >> 16);
        ((uint16_t*)Vl[buf][n4 + 2])[k] = (uint16_t)vl2.y;
        ((uint16_t*)Vl[buf][n4 + 3])[k] = (uint16_t)(vl2.y >> 16);
    };

    loadV(0);
    stageV(0);
    __syncthreads();

    for (int kt = 0; kt < nkt; kt++) {
        const int buf = kt & 1;
        if (kt + 1 < nkt) loadV(kt + 1);

        const int k0 = kt * 16;
        float2 v00 = *(float2*)&row0[k0 + 2 * q];
        float2 v02 = *(float2*)&row0[k0 + 2 * q + 8];
        float2 v10 = *(float2*)&row1[k0 + 2 * q];
        float2 v12 = *(float2*)&row1[k0 + 2 * q + 8];

        const int j0 = k0 + 2 * q, j2 = j0 + 8;
        float p00x = (j0     <= mg0) ? __expf(v00.x - mx0) * iv0 : 0.f;
        float p00y = (j0 + 1 <= mg0) ? __expf(v00.y - mx0) * iv0 : 0.f;
        float p02x = (j2     <= mg0) ? __expf(v02.x - mx0) * iv0 : 0.f;
        float p02y = (j2 + 1 <= mg0) ? __expf(v02.y - mx0) * iv0 : 0.f;
        float p10x = (j0     <= mg1) ? __expf(v10.x - mx1) * iv1 : 0.f;
        float p10y = (j0 + 1 <= mg1) ? __expf(v10.y - mx1) * iv1 : 0.f;
        float p12x = (j2     <= mg1) ? __expf(v12.x - mx1) * iv1 : 0.f;
        float p12y = (j2 + 1 <= mg1) ? __expf(v12.y - mx1) * iv1 : 0.f;

        *(float2*)&row0[j0] = make_float2(p00x, p00y);
        *(float2*)&row0[j2] = make_float2(p02x, p02y);
        *(float2*)&row1[j0] = make_float2(p10x, p10y);
        *(float2*)&row1[j2] = make_float2(p12x, p12y);

        uint32_t afh[4], afl[4];
        split2(p00x, p00y, afh[0], afl[0]);
        split2(p10x, p10y, afh[1], afl[1]);
        split2(p02x, p02y, afh[2], afl[2]);
        split2(p12x, p12y, afh[3], afl[3]);

#pragma unroll
        for (int j = 0; j < 8; j++) {
            const int n = j * 8 + g;
            uint32_t bfh[2] = {Vh[buf][n][q], Vh[buf][n][q + 4]};
            uint32_t bfl[2] = {Vl[buf][n][q], Vl[buf][n][q + 4]};
            mma_bf16(acc[j], afh, bfl);
            mma_bf16(acc[j], afl, bfh);
            mma_bf16(acc[j], afh, bfh);
        }

        if (kt + 1 < nkt) {
            stageV(buf ^ 1);
            __syncthreads();
        }
    }

    // ---- zero-fill tail columns [m0+128, S) (stores only)
    {
        const int tail0 = m0 + 128;
        if (tail0 < S_) {
            const int rloc = t >> 1;
            const int half = t & 1;
            float* rw = wz + (long long)(m0 + rloc) * S_ + tail0;
            const int ntail = S_ - tail0;
            const float4 z4 = make_float4(0.f, 0.f, 0.f, 0.f);
            for (int j = half * 4; j < ntail; j += 8) *(float4*)&rw[j] = z4;
        }
    }

    // ---- epilogue: presplit pairs -> g_aoh/g_aol [b,s][h*32 + pair]
    const size_t base0 =
        ((size_t)(b * S_ + mg0)) * (NH_ * HD_ / 2) + (size_t)h * (HD_ / 2);
    const size_t base1 =
        ((size_t)(b * S_ + mg1)) * (NH_ * HD_ / 2) + (size_t)h * (HD_ / 2);
#pragma unroll
    for (int j = 0; j < 8; j++) {
        const int pr = j * 4 + q;  // (j*8 + 2q)/2
        uint32_t hh, ll;
        split2(acc[j][0], acc[j][1], hh, ll);
        g_aoh[base0 + pr] = hh;
        g_aol[base0 + pr] = ll;
        split2(acc[j][2], acc[j][3], hh, ll);
        g_aoh[base1 + pr] = hh;
        g_aol[base1 + pr] = ll;
    }
}

// ---------------------------------------------------------------------------
// Launch
// ---------------------------------------------------------------------------
extern "C" void kernel_launch(void* const* d_in, const int* in_sizes, int n_in,
                              void* d_out, int out_size) {
    const float* hidden = (const float*)d_in[0];
    const float* cs     = (const float*)d_in[1];
    const float* sn     = (const float*)d_in[2];
    // d_in[3] = attention_mask: causal 0/-1e9, applied analytically (unused)
    const float* Wq = (const float*)d_in[4];
    const float* Wk = (const float*)d_in[5];
    const float* Wv = (const float*)d_in[6];
    const float* Wo = (const float*)d_in[7];

    float* out = (float*)d_out;
    float* w   = out + OUT_W_OFFSET;

    uint32_t *pqh, *pql, *pkh, *pkl, *paoh, *paol;
    cudaGetSymbolAddress((void**)&pqh,  g_qh);
    cudaGetSymbolAddress((void**)&pql,  g_ql);
    cudaGetSymbolAddress((void**)&pkh,  g_kh);
    cudaGetSymbolAddress((void**)&pkl,  g_kl);
    cudaGetSymbolAddress((void**)&paoh, g_aoh);
    cudaGetSymbolAddress((void**)&paol, g_aol);

    const int M = B_ * S_;  // 4096

    // 1) Fused QKV projection + RoPE: X @ [Wq|Wk|Wv]^T, N = 3072.
    //    Outputs presplit bf16 hi/lo pairs (q/k permuted; v natural).
    gemm_bf16x3<128, 64, 4, 2, false, false, true, true, false, EpiQKV>
        <<<dim3(NQKV_ / 64, M / 128, 1), 256>>>(
            hidden, nullptr, nullptr, Wq, nullptr, nullptr, M, NQKV_, HID_, 0,
            0, 1, EpiQKV{}, Wk, Wv, NQ_, NQK_, cs, sn);

    // 2) logits = q @ k^T * scale (presplit operands; causal tile skip)
    gemm_bf16x3<128, 64, 4, 2, true, true, false, false, true, EpiLogits>
        <<<dim3(S_ / 64, S_ / 128, B_ * NH_), 256>>>(
            nullptr, pqh, pql, nullptr, pkh, pkl, S_, S_, HD_,
            (long long)S_ * (HD_ / 2), (long long)S_ * (HD_ / 2), NREP_,
            EpiLogits{w});

    // 3) fused causal softmax + P@V (writes attn_weights and presplit ao)
    softmax_pv_kernel<<<dim3(S_ / 128, B_ * NH_), 256>>>(w);

    // 4) out = ao @ Wo^T (A presplit, B fp32 split)
    gemm_bf16x3<128, 64, 4, 2, true, false, false, false, false, EpiOut>
        <<<dim3(HID_ / 64, M / 128, 1), 256>>>(
            nullptr, paoh, paol, Wo, nullptr, nullptr, M, HID_, NH_ * HD_, 0,
            0, 1, EpiOut{out});
}